// round 5
// baseline (speedup 1.0000x reference)
#include <cuda_runtime.h>
#include <cuda_bf16.h>
#include <math.h>

// T=2048 tokens, H=2048 hidden, V=32000 vocab, E=16 experts, top-2.
// Inputs: hidden_states (T*H f32), gate_w (16*H f32), expert_biases (16*V f32).
// Output: bias (T*V f32) then aux_loss (1 f32).

#define NUM_E 16
#define MAX_T 8192

__device__ float  g_probs[MAX_T * NUM_E];   // softmax probs per token
__device__ float4 g_meta[MAX_T];            // (w0, w1, bitcast i0, bitcast i1)

// ---------------------------------------------------------------------------
// Kernel 1: gate logits + softmax + top-2.
// Block = 256 threads = 8 warps, 4 tokens. Warp w = (expert group w&3) x
// (H-half w>>2): acc[4 experts][4 tokens] = 16 regs. grid = T/4 = 512 blocks
// -> 4096 warps (~7/SMSP). Explicit h prefetch double-buffer hides DRAM lat.
// ---------------------------------------------------------------------------
__global__ __launch_bounds__(256) void gate_kernel(
    const float* __restrict__ hidden,
    const float* __restrict__ gate_w,
    int H)
{
    const int tid  = threadIdx.x;
    const int lane = tid & 31;
    const int warp = tid >> 5;
    const int eg   = warp & 3;       // experts 4*eg .. 4*eg+3
    const int hh   = warp >> 2;      // H half
    const int Hf4  = H >> 2;         // 512
    const int half = Hf4 >> 1;       // 256
    const int t0   = blockIdx.x * 4;

    const float4* __restrict__ hf4 = (const float4*)hidden;
    const float4* __restrict__ gf4 = (const float4*)gate_w;

    __shared__ float red[8][4][4];   // [warp][local expert][token]
    __shared__ float slog[4][NUM_E];

    float acc[4][4];
    #pragma unroll
    for (int e = 0; e < 4; e++)
        #pragma unroll
        for (int t = 0; t < 4; t++) acc[e][t] = 0.0f;

    const int nIter = half >> 5;     // 8
    int i = hh * half + lane;

    float4 h[4], hn[4];
    #pragma unroll
    for (int t = 0; t < 4; t++)
        h[t] = hf4[(size_t)(t0 + t) * Hf4 + i];

    for (int it = 0; it < nIter; ++it) {
        const int inext = i + 32;
        if (it + 1 < nIter) {
            #pragma unroll
            for (int t = 0; t < 4; t++)
                hn[t] = hf4[(size_t)(t0 + t) * Hf4 + inext];
        }
        #pragma unroll
        for (int e = 0; e < 4; e++) {
            float4 g = __ldg(&gf4[(size_t)(eg * 4 + e) * Hf4 + i]);
            #pragma unroll
            for (int t = 0; t < 4; t++)
                acc[e][t] += h[t].x*g.x + h[t].y*g.y + h[t].z*g.z + h[t].w*g.w;
        }
        #pragma unroll
        for (int t = 0; t < 4; t++) h[t] = hn[t];
        i = inext;
    }

    // intra-warp butterfly reduction (deterministic)
    #pragma unroll
    for (int e = 0; e < 4; e++) {
        #pragma unroll
        for (int t = 0; t < 4; t++) {
            float v = acc[e][t];
            v += __shfl_xor_sync(0xffffffffu, v, 16);
            v += __shfl_xor_sync(0xffffffffu, v, 8);
            v += __shfl_xor_sync(0xffffffffu, v, 4);
            v += __shfl_xor_sync(0xffffffffu, v, 2);
            v += __shfl_xor_sync(0xffffffffu, v, 1);
            if (lane == 0) red[warp][e][t] = v;
        }
    }
    __syncthreads();

    // combine the two H-halves: one thread per (expert, token) cell
    if (tid < 64) {
        int e = tid >> 2, t = tid & 3;         // e in [0,16), t in [0,4)
        int g = e >> 2, el = e & 3;            // warp group / local expert
        slog[t][e] = red[g][el][t] + red[g + 4][el][t];
    }
    __syncthreads();

    // per-token softmax + top-2
    if (tid < 4) {
        const int tok = t0 + tid;
        float l[NUM_E];
        float mx = -1e30f;
        #pragma unroll
        for (int e = 0; e < NUM_E; e++) { l[e] = slog[tid][e]; mx = fmaxf(mx, l[e]); }
        float sum = 0.0f;
        float p[NUM_E];
        #pragma unroll
        for (int e = 0; e < NUM_E; e++) { p[e] = expf(l[e] - mx); sum += p[e]; }
        float inv = 1.0f / sum;
        int   i0 = 0, i1 = -1;
        float p0 = -1.0f, p1 = -1.0f;
        #pragma unroll
        for (int e = 0; e < NUM_E; e++) {
            float pe = p[e] * inv;
            g_probs[(size_t)tok * NUM_E + e] = pe;
            if (pe > p0)      { p1 = p0; i1 = i0; p0 = pe; i0 = e; }
            else if (pe > p1) { p1 = pe; i1 = e; }
        }
        float s2 = p0 + p1;
        float4 m;
        m.x = p0 / s2;
        m.y = p1 / s2;
        m.z = __int_as_float(i0);
        m.w = __int_as_float(i1);
        g_meta[tok] = m;
    }
}

// ---------------------------------------------------------------------------
// Kernel 2: aux loss. Single block, float4 coalesced, deterministic.
// ---------------------------------------------------------------------------
__global__ __launch_bounds__(256) void aux_kernel(float* __restrict__ out_aux, int T)
{
    __shared__ float4 s4[256];
    __shared__ float4 su4[4];
    const int tid = threadIdx.x;
    const int e4  = tid & 3;
    const int c   = tid >> 2;

    const float4* __restrict__ probs4 = (const float4*)g_probs;

    float4 sum = make_float4(0.f, 0.f, 0.f, 0.f);
    for (int t = c; t < T; t += 64) {
        float4 v = probs4[(size_t)t * 4 + e4];
        sum.x += v.x; sum.y += v.y; sum.z += v.z; sum.w += v.w;
    }
    s4[tid] = sum;
    __syncthreads();

    if (tid < 4) {
        float4 u = make_float4(0.f, 0.f, 0.f, 0.f);
        #pragma unroll
        for (int cc = 0; cc < 64; cc++) {
            float4 v = s4[cc * 4 + tid];
            u.x += v.x; u.y += v.y; u.z += v.z; u.w += v.w;
        }
        su4[tid] = u;
    }
    __syncthreads();

    if (tid == 0) {
        float invT = 1.0f / (float)T;
        float aux = 0.0f;
        #pragma unroll
        for (int q = 0; q < 4; q++) {
            float4 u = su4[q];
            float a = u.x * invT, b = u.y * invT, cc = u.z * invT, d = u.w * invT;
            aux += a * logf(a) + b * logf(b) + cc * logf(cc) + d * logf(d);
        }
        out_aux[0] = aux * (float)NUM_E;
    }
}

// ---------------------------------------------------------------------------
// Kernel 3: bias = w0*B[i0] + w1*B[i1]. 262 MB of stores (write-bound).
// CHUNK = 512 floats = 2048 B = 16 whole L2 lines; streaming stores.
// TOK_GRP = 256 halves the redundant sB staging vs 128.
// ---------------------------------------------------------------------------
#define CHUNK_F4 128          // 512 floats = 2048 B per expert per chunk
#define TOK_GRP  256

__global__ __launch_bounds__(256) void bias_kernel(
    const float* __restrict__ biases,
    float* __restrict__ out,
    int V)
{
    __shared__ float4 sB[NUM_E][CHUNK_F4];   // 32 KB
    __shared__ float4 smeta[TOK_GRP];        // 4 KB

    const int tid   = threadIdx.x;
    const int lane  = tid & 31;
    const int warp  = tid >> 5;
    const int Vf4   = V >> 2;                       // 8000
    const int vbase = blockIdx.x * CHUNK_F4;        // 2048B-aligned
    const int clen  = min(CHUNK_F4, Vf4 - vbase);   // 128 or 64 (tail)
    const int tbase = blockIdx.y * TOK_GRP;

    const float4* __restrict__ bf4 = (const float4*)biases;
    float4* __restrict__ of4 = (float4*)out;

    for (int i = tid; i < NUM_E * CHUNK_F4; i += 256) {
        int e = i >> 7, p = i & (CHUNK_F4 - 1);
        if (p < clen) sB[e][p] = bf4[(size_t)e * Vf4 + vbase + p];
    }
    smeta[tid] = g_meta[tbase + tid];
    __syncthreads();

    // warp-per-token, lane-contiguous 16B stores (512B/warp bursts)
    for (int t = warp; t < TOK_GRP; t += 8) {
        float4 m = smeta[t];
        const float w0 = m.x, w1 = m.y;
        const int i0 = __float_as_int(m.z);
        const int i1 = __float_as_int(m.w);
        float4* __restrict__ orow = &of4[(size_t)(tbase + t) * Vf4 + vbase];
        #pragma unroll 4
        for (int p = lane; p < clen; p += 32) {
            float4 a = sB[i0][p];
            float4 b = sB[i1][p];
            float4 r;
            r.x = w0 * a.x + w1 * b.x;
            r.y = w0 * a.y + w1 * b.y;
            r.z = w0 * a.z + w1 * b.z;
            r.w = w0 * a.w + w1 * b.w;
            __stcs(&orow[p], r);
        }
    }
}

// ---------------------------------------------------------------------------
extern "C" void kernel_launch(void* const* d_in, const int* in_sizes, int n_in,
                              void* d_out, int out_size)
{
    const float* hidden = (const float*)d_in[0];
    const float* gate_w = (const float*)d_in[1];
    const float* biases = (const float*)d_in[2];
    float* out = (float*)d_out;

    const int H = in_sizes[1] / NUM_E;         // 2048
    const int T = in_sizes[0] / H;             // 2048
    const int V = in_sizes[2] / NUM_E;         // 32000

    // 1) gating: 4 tokens per block, 8 warps (4 expert groups x 2 H-halves)
    gate_kernel<<<T / 4, 256>>>(hidden, gate_w, H);

    // 2) bias gather+blend
    const int nchunks = (V / 4 + CHUNK_F4 - 1) / CHUNK_F4;   // 63
    dim3 grid(nchunks, T / TOK_GRP);                         // (63, 8)
    bias_kernel<<<grid, 256>>>(biases, out, V);

    // 3) aux loss -> out[T*V]
    aux_kernel<<<1, 256>>>(out + (size_t)T * V, T);
}